// round 15
// baseline (speedup 1.0000x reference)
#include <cuda_runtime.h>
#include <math.h>
#include <cstdint>

#define BATCH 4
#define CIN   64
#define HH    160
#define WW    160
#define GRP   8
#define KK9   9
#define HW    (HH*WW)

// scratch: dy, dx, mask each [B][G*9][H][W]
#define SCR_N (BATCH*GRP*KK9*HH*WW)   // 7,372,800
__device__ float g_scr[3*SCR_N];

// NHWC transposes: [B][HW][CIN]
__device__ float g_xt[(size_t)BATCH*HW*CIN];
__device__ float g_ft[(size_t)BATCH*HW*CIN];

// packed tf32 B fragments, offset conv: [t(72)][lane(32)][ntp(28)] float2
// (pairs of n-tiles contiguous per lane -> LDG.128; ntp 27 = zero pad)
#define NBT (72*32*28)
__device__ float2 g_bfrag[NBT];

// packed tf32 B fragments, dcn: [t(72)][lane(32)][nt(8)] float2
#define NBT2 (72*32*8)
__device__ float2 g_bfrag2[NBT2];

__device__ __forceinline__ uint32_t f2tf32(float v) {
    uint32_t r;
    asm("cvt.rna.tf32.f32 %0, %1;" : "=r"(r) : "f"(v));
    return r;
}

#define MMA_TF32(d, a, b0, b1) \
    asm volatile("mma.sync.aligned.m16n8k8.row.col.f32.tf32.tf32.f32 " \
        "{%0,%1,%2,%3}, {%4,%5,%6,%7}, {%8,%9}, {%0,%1,%2,%3};" \
        : "+f"((d)[0]), "+f"((d)[1]), "+f"((d)[2]), "+f"((d)[3]) \
        : "r"((a)[0]), "r"((a)[1]), "r"((a)[2]), "r"((a)[3]), \
          "r"(b0), "r"(b1))

// ---------------------------------------------------------------------------
// Transpose NCHW -> NHWC for x (z=0..3) and feat (z=4..7) in one launch
// ---------------------------------------------------------------------------
__global__ __launch_bounds__(256)
void transpose2_kernel(const float* __restrict__ xin,
                       const float* __restrict__ feat)
{
    __shared__ float tile[32][33];
    const int z  = blockIdx.z;
    const int b  = z & 3;
    const int c0 = blockIdx.y * 32;
    const int p0 = blockIdx.x * 32;
    const int tx = threadIdx.x & 31;
    const int ty = threadIdx.x >> 5;

    const float* src = (z < 4) ? xin : feat;
    float* dst = (z < 4) ? g_xt : g_ft;

    const float* sb = src + (size_t)b * CIN * HW;
#pragma unroll
    for (int j = 0; j < 4; j++)
        tile[ty + 8*j][tx] = sb[(size_t)(c0 + ty + 8*j) * HW + p0 + tx];
    __syncthreads();
    float* db = dst + (size_t)b * HW * CIN;
#pragma unroll
    for (int j = 0; j < 4; j++)
        db[(size_t)(p0 + ty + 8*j) * CIN + c0 + tx] = tile[tx][ty + 8*j];
}

// ---------------------------------------------------------------------------
// Pack w_off, kk-major, lane-contiguous pairs:
// idx = (t*32 + lane)*28 + nt ; t -> kk = t>>3, cg = t&7
// ---------------------------------------------------------------------------
__global__ __launch_bounds__(256)
void pack_w_kernel(const float* __restrict__ w_off)
{
    int e = blockIdx.x * 256 + threadIdx.x;
    if (e >= NBT) return;
    int nt   = e % 28;
    int r    = e / 28;
    int lane = r & 31;
    int t    = r >> 5;
    float2 v = make_float2(0.f, 0.f);
    if (nt < 27) {
        int n  = nt * 8 + (lane >> 2);
        int c  = lane & 3;
        int kk = t >> 3;
        int ch = (t & 7) * 8 + 2 * c;
        v.x = __uint_as_float(f2tf32(w_off[(size_t)n * 576 + ch * 9 + kk]));
        v.y = __uint_as_float(f2tf32(w_off[(size_t)n * 576 + (ch + 1) * 9 + kk]));
    }
    g_bfrag[e] = v;
}

// ---------------------------------------------------------------------------
// Pack w_dcn, lane-contiguous: idx = (t*32 + lane)*8 + nt ; t = g*9+k
// ---------------------------------------------------------------------------
__global__ __launch_bounds__(256)
void pack_wd_kernel(const float* __restrict__ w_dcn)
{
    int e = blockIdx.x * 256 + threadIdx.x;
    if (e >= NBT2) return;
    int nt   = e & 7;
    int r    = e >> 3;
    int lane = r & 31;
    int t    = r >> 5;
    int g = t / 9, k = t % 9;
    int n = nt * 8 + (lane >> 2);
    int c = lane & 3;
    float2 v;
    v.x = __uint_as_float(f2tf32(w_dcn[((size_t)n * CIN + g * 8 + c) * 9 + k]));
    v.y = __uint_as_float(f2tf32(w_dcn[((size_t)n * CIN + g * 8 + c + 4) * 9 + k]));
    g_bfrag2[e] = v;
}

// ---------------------------------------------------------------------------
// Kernel A: implicit-GEMM 3x3 conv via mma.sync tf32
// NHWC feat, kk-major K, float2 clamped gathers, 2-deep prefetch,
// float4-paired B loads (14 LDG.128/ktile)
// ---------------------------------------------------------------------------
__device__ __forceinline__ void emit_off(int co, float v, int b, int p,
                                         const float* __restrict__ b_off) {
    v += __ldg(b_off + co);
    if (co < 144) {
        int g = co / 18, r = co % 18, k = r >> 1;
        float* dst = (r & 1) ? (g_scr + SCR_N) : g_scr;   // dx : dy
        dst[(b * GRP * KK9 + g * KK9 + k) * HW + p] = v;
    } else {
        int cm = co - 144, g = cm / 9, k = cm % 9;
        g_scr[2 * SCR_N + (b * GRP * KK9 + g * KK9 + k) * HW + p] =
            1.f / (1.f + expf(-v));
    }
}

__global__ __launch_bounds__(256)
void offset_conv_mma(const float* __restrict__ b_off)
{
    const int tid  = threadIdx.x;
    const int warp = tid >> 5, lane = tid & 31;
    const int b  = blockIdx.y;
    const int p0 = blockIdx.x * 128;

    const int m0 = warp * 16 + (lane >> 2);
    const int pA = p0 + m0, pB = pA + 8;
    const int yA = pA / WW, xA = pA % WW;
    const int yB = pB / WW, xB = pB % WW;
    const float* fbt = g_ft + (size_t)b * HW * CIN;

    float acc[27][4];
#pragma unroll
    for (int i = 0; i < 27; i++)
#pragma unroll
        for (int j = 0; j < 4; j++) acc[i][j] = 0.f;

    const int c2 = (lane & 3) * 2;

    auto build_a = [&](int t, uint32_t* a) {
        int kk  = t >> 3;
        int ch  = (t & 7) * 8 + c2;
        int kdy = (kk > 5) ? 2 : ((kk > 2) ? 1 : 0);
        int kdx = kk - kdy * 3;
        int gyA = yA + kdy - 1, gxA = xA + kdx - 1;
        int gyB = yB + kdy - 1, gxB = xB + kdx - 1;
        float mA = (((unsigned)gyA < HH) && ((unsigned)gxA < WW)) ? 1.f : 0.f;
        float mB = (((unsigned)gyB < HH) && ((unsigned)gxB < WW)) ? 1.f : 0.f;
        int cyA = min(max(gyA, 0), HH-1), cxA = min(max(gxA, 0), WW-1);
        int cyB = min(max(gyB, 0), HH-1), cxB = min(max(gxB, 0), WW-1);
        float2 vA = __ldg((const float2*)(fbt + (size_t)(cyA * WW + cxA) * CIN + ch));
        float2 vB = __ldg((const float2*)(fbt + (size_t)(cyB * WW + cxB) * CIN + ch));
        a[0] = f2tf32(vA.x * mA); a[1] = f2tf32(vB.x * mB);
        a[2] = f2tf32(vA.y * mA); a[3] = f2tf32(vB.y * mB);
    };

    uint32_t a0[4], a1[4];
    build_a(0, a0);
    build_a(1, a1);

#pragma unroll 1
    for (int t = 0; t < 72; t++) {
        uint32_t an[4] = {0u, 0u, 0u, 0u};
        if (t < 70) build_a(t + 2, an);

        const float4* bt = (const float4*)(g_bfrag + ((size_t)t * 32 + lane) * 28);
        // batch 1: pairs 0..6 -> n-tiles 0..13
        {
            float4 bb[7];
#pragma unroll
            for (int j = 0; j < 7; j++) bb[j] = __ldg(bt + j);
#pragma unroll
            for (int j = 0; j < 7; j++) {
                MMA_TF32(acc[2*j],   a0, __float_as_uint(bb[j].x), __float_as_uint(bb[j].y));
                MMA_TF32(acc[2*j+1], a0, __float_as_uint(bb[j].z), __float_as_uint(bb[j].w));
            }
        }
        // batch 2: pairs 7..13 -> n-tiles 14..26 (27 = pad, skipped)
        {
            float4 bb[7];
#pragma unroll
            for (int j = 0; j < 7; j++) bb[j] = __ldg(bt + 7 + j);
#pragma unroll
            for (int j = 0; j < 7; j++) {
                MMA_TF32(acc[14+2*j], a0, __float_as_uint(bb[j].x), __float_as_uint(bb[j].y));
                if (j < 6)
                    MMA_TF32(acc[15+2*j], a0, __float_as_uint(bb[j].z), __float_as_uint(bb[j].w));
            }
        }

#pragma unroll
        for (int j = 0; j < 4; j++) { a0[j] = a1[j]; a1[j] = an[j]; }
    }

#pragma unroll
    for (int nt = 0; nt < 27; nt++) {
#pragma unroll
        for (int i = 0; i < 4; i++) {
            int p  = (i >= 2) ? pB : pA;
            int co = nt * 8 + c2 + (i & 1);
            emit_off(co, acc[nt][i], b, p, b_off);
        }
    }
}

// ---------------------------------------------------------------------------
// Kernel B: modulated deformable conv via mma.sync tf32, NHWC gathers,
// pair-rotated N, 2-deep prefetch, float4-paired B loads (4 LDG.128/ktile)
// ---------------------------------------------------------------------------
__global__ __launch_bounds__(256)
void dcn_mma(const float* __restrict__ b_dcn,
             float* __restrict__ out)
{
    const int tid  = threadIdx.x;
    const int warp = tid >> 5, lane = tid & 31;
    const int b  = blockIdx.y;
    const int p0 = blockIdx.x * 128;
    const int rotp = warp & 3;          // pair-granular rotation

    const int m0 = warp * 16 + (lane >> 2);
    const int pA = p0 + m0, pB = pA + 8;
    const int yA = pA / WW, xA = pA % WW;
    const int yB = pB / WW, xB = pB % WW;

    const float* dyp = g_scr;
    const float* dxp = g_scr + SCR_N;
    const float* mp  = g_scr + 2*SCR_N;
    const float* xtb = g_xt + (size_t)b * HW * CIN;

    float acc[8][4];                    // acc[2j+h] holds nt 2*((j+rotp)&3)+h
#pragma unroll
    for (int i = 0; i < 8; i++)
#pragma unroll
        for (int j = 0; j < 4; j++) acc[i][j] = 0.f;

    const int c = lane & 3;

    auto build_a = [&](int t, uint32_t* a) {
        int g = t / 9, k = t - g * 9;
        int kdy = (k > 5) ? 2 : ((k > 2) ? 1 : 0);
        int kdx = k - kdy * 3;
        const int sb = (b * 72 + t) * HW;
        const float* xc = xtb + g * 8 + c;

        float vA0, vA4, vB0, vB4;
        {   // row pA
            float dy = __ldg(dyp + sb + pA), dx = __ldg(dxp + sb + pA);
            float mv = __ldg(mp + sb + pA);
            float py = (float)(yA + kdy - 1) + dy;
            float px = (float)(xA + kdx - 1) + dx;
            float fy = floorf(py), fx = floorf(px);
            int y0 = (int)fy, x0 = (int)fx;
            float ly = py - fy, lx = px - fx;
            bool vy0 = ((unsigned)y0 < HH), vy1 = ((unsigned)(y0+1) < HH);
            bool vx0 = ((unsigned)x0 < WW), vx1 = ((unsigned)(x0+1) < WW);
            int y0c = min(max(y0,0),HH-1), y1c = min(max(y0+1,0),HH-1);
            int x0c = min(max(x0,0),WW-1), x1c = min(max(x0+1,0),WW-1);
            float w00 = (1.f-ly)*(1.f-lx)*mv*((vy0&&vx0)?1.f:0.f);
            float w01 = (1.f-ly)*lx      *mv*((vy0&&vx1)?1.f:0.f);
            float w10 = ly      *(1.f-lx)*mv*((vy1&&vx0)?1.f:0.f);
            float w11 = ly      *lx      *mv*((vy1&&vx1)?1.f:0.f);
            int i00 = (y0c*WW+x0c)*CIN, i01 = (y0c*WW+x1c)*CIN;
            int i10 = (y1c*WW+x0c)*CIN, i11 = (y1c*WW+x1c)*CIN;
            vA0 = w00*__ldg(xc+i00)+w01*__ldg(xc+i01)+w10*__ldg(xc+i10)+w11*__ldg(xc+i11);
            vA4 = w00*__ldg(xc+i00+4)+w01*__ldg(xc+i01+4)+w10*__ldg(xc+i10+4)+w11*__ldg(xc+i11+4);
        }
        {   // row pB
            float dy = __ldg(dyp + sb + pB), dx = __ldg(dxp + sb + pB);
            float mv = __ldg(mp + sb + pB);
            float py = (float)(yB + kdy - 1) + dy;
            float px = (float)(xB + kdx - 1) + dx;
            float fy = floorf(py), fx = floorf(px);
            int y0 = (int)fy, x0 = (int)fx;
            float ly = py - fy, lx = px - fx;
            bool vy0 = ((unsigned)y0 < HH), vy1 = ((unsigned)(y0+1) < HH);
            bool vx0 = ((unsigned)x0 < WW), vx1 = ((unsigned)(x0+1) < WW);
            int y0c = min(max(y0,0),HH-1), y1c = min(max(y0+1,0),HH-1);
            int x0c = min(max(x0,0),WW-1), x1c = min(max(x0+1,0),WW-1);
            float w00 = (1.f-ly)*(1.f-lx)*mv*((vy0&&vx0)?1.f:0.f);
            float w01 = (1.f-ly)*lx      *mv*((vy0&&vx1)?1.f:0.f);
            float w10 = ly      *(1.f-lx)*mv*((vy1&&vx0)?1.f:0.f);
            float w11 = ly      *lx      *mv*((vy1&&vx1)?1.f:0.f);
            int i00 = (y0c*WW+x0c)*CIN, i01 = (y0c*WW+x1c)*CIN;
            int i10 = (y1c*WW+x0c)*CIN, i11 = (y1c*WW+x1c)*CIN;
            vB0 = w00*__ldg(xc+i00)+w01*__ldg(xc+i01)+w10*__ldg(xc+i10)+w11*__ldg(xc+i11);
            vB4 = w00*__ldg(xc+i00+4)+w01*__ldg(xc+i01+4)+w10*__ldg(xc+i10+4)+w11*__ldg(xc+i11+4);
        }
        a[0] = f2tf32(vA0); a[1] = f2tf32(vB0);
        a[2] = f2tf32(vA4); a[3] = f2tf32(vB4);
    };

    uint32_t a0[4], a1[4];
    build_a(0, a0);
    build_a(1, a1);

#pragma unroll 1
    for (int t = 0; t < 72; t++) {
        uint32_t an[4] = {0u, 0u, 0u, 0u};
        if (t < 70) build_a(t + 2, an);

        const float4* bt = (const float4*)(g_bfrag2 + ((size_t)t * 32 + lane) * 8);
        float4 bb[4];
#pragma unroll
        for (int j = 0; j < 4; j++)
            bb[j] = __ldg(bt + ((j + rotp) & 3));
#pragma unroll
        for (int j = 0; j < 4; j++) {
            MMA_TF32(acc[2*j],   a0, __float_as_uint(bb[j].x), __float_as_uint(bb[j].y));
            MMA_TF32(acc[2*j+1], a0, __float_as_uint(bb[j].z), __float_as_uint(bb[j].w));
        }

#pragma unroll
        for (int j = 0; j < 4; j++) { a0[j] = a1[j]; a1[j] = an[j]; }
    }

#pragma unroll
    for (int j = 0; j < 4; j++) {
        int ntp = (j + rotp) & 3;
#pragma unroll
        for (int h = 0; h < 2; h++) {
            int nt = 2 * ntp + h;
#pragma unroll
            for (int e = 0; e < 4; e++) {
                int o = nt * 8 + c * 2 + (e & 1);
                int p = (e >= 2) ? pB : pA;
                out[((size_t)b * 64 + o) * HW + p] = acc[2*j+h][e] + __ldg(b_dcn + o);
            }
        }
    }
}

// ---------------------------------------------------------------------------
extern "C" void kernel_launch(void* const* d_in, const int* in_sizes, int n_in,
                              void* d_out, int out_size)
{
    const float* x     = (const float*)d_in[0];
    const float* feat  = (const float*)d_in[1];
    const float* w_off = (const float*)d_in[2];
    const float* b_off = (const float*)d_in[3];
    const float* w_dcn = (const float*)d_in[4];
    const float* b_dcn = (const float*)d_in[5];
    float* out = (float*)d_out;

    pack_w_kernel<<<(NBT + 255) / 256, 256>>>(w_off);
    pack_wd_kernel<<<(NBT2 + 255) / 256, 256>>>(w_dcn);

    dim3 gT(HW / 32, CIN / 32, BATCH * 2);  // 800 x 2 x 8 (x + feat)
    transpose2_kernel<<<gT, 256>>>(x, feat);

    dim3 gA(HW / 128, BATCH);           // 200 x 4
    offset_conv_mma<<<gA, 256>>>(b_off);

    dim3 gB(HW / 128, BATCH);           // 200 x 4
    dcn_mma<<<gB, 256>>>(b_dcn, out);
}

// round 16
// speedup vs baseline: 2.1487x; 2.1487x over previous
#include <cuda_runtime.h>
#include <math.h>
#include <cstdint>

#define BATCH 4
#define CIN   64
#define HH    160
#define WW    160
#define GRP   8
#define KK9   9
#define HW    (HH*WW)

// scratch: dy, dx, mask each [B][G*9][H][W]
#define SCR_N (BATCH*GRP*KK9*HH*WW)   // 7,372,800
__device__ float g_scr[3*SCR_N];

// NHWC transposes: [B][HW][CIN]
__device__ float g_xt[(size_t)BATCH*HW*CIN];
__device__ float g_ft[(size_t)BATCH*HW*CIN];

// packed tf32 B fragments, offset conv: [t(72)][nt(27)][lane(32)] float2
// t = kk*8 + cg ; slot c <-> ch cg*8+2c (.x), slot c+4 <-> ch cg*8+2c+1 (.y)
#define NBT (72*27*32)
__device__ float2 g_bfrag[NBT];

// packed tf32 B fragments, dcn: [t(72)][nt(8)][lane(32)] float2
#define NBT2 (72*8*32)
__device__ float2 g_bfrag2[NBT2];

__device__ __forceinline__ uint32_t f2tf32(float v) {
    uint32_t r;
    asm("cvt.rna.tf32.f32 %0, %1;" : "=r"(r) : "f"(v));
    return r;
}

#define MMA_TF32(d, a, b0, b1) \
    asm volatile("mma.sync.aligned.m16n8k8.row.col.f32.tf32.tf32.f32 " \
        "{%0,%1,%2,%3}, {%4,%5,%6,%7}, {%8,%9}, {%0,%1,%2,%3};" \
        : "+f"((d)[0]), "+f"((d)[1]), "+f"((d)[2]), "+f"((d)[3]) \
        : "r"((a)[0]), "r"((a)[1]), "r"((a)[2]), "r"((a)[3]), \
          "r"(b0), "r"(b1))

// ---------------------------------------------------------------------------
// Transpose NCHW -> NHWC for x (z=0..3) and feat (z=4..7) in one launch
// ---------------------------------------------------------------------------
__global__ __launch_bounds__(256)
void transpose2_kernel(const float* __restrict__ xin,
                       const float* __restrict__ feat)
{
    __shared__ float tile[32][33];
    const int z  = blockIdx.z;
    const int b  = z & 3;
    const int c0 = blockIdx.y * 32;
    const int p0 = blockIdx.x * 32;
    const int tx = threadIdx.x & 31;
    const int ty = threadIdx.x >> 5;

    const float* src = (z < 4) ? xin : feat;
    float* dst = (z < 4) ? g_xt : g_ft;

    const float* sb = src + (size_t)b * CIN * HW;
#pragma unroll
    for (int j = 0; j < 4; j++)
        tile[ty + 8*j][tx] = sb[(size_t)(c0 + ty + 8*j) * HW + p0 + tx];
    __syncthreads();
    float* db = dst + (size_t)b * HW * CIN;
#pragma unroll
    for (int j = 0; j < 4; j++)
        db[(size_t)(p0 + ty + 8*j) * CIN + c0 + tx] = tile[tx][ty + 8*j];
}

// ---------------------------------------------------------------------------
// Pack w_off, kk-major: ktile t -> kk = t>>3, cg = t&7
// layout [t][nt][lane] (lane-coalesced)
// ---------------------------------------------------------------------------
__global__ __launch_bounds__(256)
void pack_w_kernel(const float* __restrict__ w_off)
{
    int e = blockIdx.x * 256 + threadIdx.x;
    if (e >= NBT) return;
    int lane = e & 31;
    int r = e >> 5;
    int nt = r % 27;
    int t  = r / 27;
    int n  = nt * 8 + (lane >> 2);
    int c  = lane & 3;
    int kk = t >> 3;
    int ch = (t & 7) * 8 + 2 * c;
    float2 v;
    v.x = __uint_as_float(f2tf32(w_off[(size_t)n * 576 + ch * 9 + kk]));
    v.y = __uint_as_float(f2tf32(w_off[(size_t)n * 576 + (ch + 1) * 9 + kk]));
    g_bfrag[e] = v;
}

// ---------------------------------------------------------------------------
// Pack w_dcn [64][64][3][3], kd = (g*9+k)*8 + c, layout [t][nt][lane]
// ---------------------------------------------------------------------------
__global__ __launch_bounds__(256)
void pack_wd_kernel(const float* __restrict__ w_dcn)
{
    int e = blockIdx.x * 256 + threadIdx.x;
    if (e >= NBT2) return;
    int lane = e & 31;
    int r = e >> 5;
    int nt = r & 7;
    int t  = r >> 3;
    int g = t / 9, k = t % 9;
    int n = nt * 8 + (lane >> 2);
    int c = lane & 3;
    float2 v;
    v.x = __uint_as_float(f2tf32(w_dcn[((size_t)n * CIN + g * 8 + c) * 9 + k]));
    v.y = __uint_as_float(f2tf32(w_dcn[((size_t)n * CIN + g * 8 + c + 4) * 9 + k]));
    g_bfrag2[e] = v;
}

// ---------------------------------------------------------------------------
// Kernel A: implicit-GEMM 3x3 conv via mma.sync tf32
// TILE_M=64, 128 thr (2 blocks/SM); NHWC feat, kk-major K,
// clamped float2 gathers, 2-deep prefetch
// ---------------------------------------------------------------------------
__device__ __forceinline__ void emit_off(int co, float v, int b, int p,
                                         const float* __restrict__ b_off) {
    v += __ldg(b_off + co);
    if (co < 144) {
        int g = co / 18, r = co % 18, k = r >> 1;
        float* dst = (r & 1) ? (g_scr + SCR_N) : g_scr;   // dx : dy
        dst[(b * GRP * KK9 + g * KK9 + k) * HW + p] = v;
    } else {
        int cm = co - 144, g = cm / 9, k = cm % 9;
        g_scr[2 * SCR_N + (b * GRP * KK9 + g * KK9 + k) * HW + p] =
            1.f / (1.f + expf(-v));
    }
}

__global__ __launch_bounds__(128)
void offset_conv_mma(const float* __restrict__ b_off)
{
    const int tid  = threadIdx.x;
    const int warp = tid >> 5, lane = tid & 31;
    const int b  = blockIdx.y;
    const int p0 = blockIdx.x * 64;

    const int m0 = warp * 16 + (lane >> 2);
    const int pA = p0 + m0, pB = pA + 8;
    const int yA = pA / WW, xA = pA % WW;
    const int yB = pB / WW, xB = pB % WW;
    const float* fbt = g_ft + (size_t)b * HW * CIN;

    float acc[27][4];
#pragma unroll
    for (int i = 0; i < 27; i++)
#pragma unroll
        for (int j = 0; j < 4; j++) acc[i][j] = 0.f;

    const int c2 = (lane & 3) * 2;

    auto build_a = [&](int t, uint32_t* a) {
        int kk  = t >> 3;
        int ch  = (t & 7) * 8 + c2;
        int kdy = (kk > 5) ? 2 : ((kk > 2) ? 1 : 0);
        int kdx = kk - kdy * 3;
        int gyA = yA + kdy - 1, gxA = xA + kdx - 1;
        int gyB = yB + kdy - 1, gxB = xB + kdx - 1;
        float mA = (((unsigned)gyA < HH) && ((unsigned)gxA < WW)) ? 1.f : 0.f;
        float mB = (((unsigned)gyB < HH) && ((unsigned)gxB < WW)) ? 1.f : 0.f;
        int cyA = min(max(gyA, 0), HH-1), cxA = min(max(gxA, 0), WW-1);
        int cyB = min(max(gyB, 0), HH-1), cxB = min(max(gxB, 0), WW-1);
        float2 vA = __ldg((const float2*)(fbt + (size_t)(cyA * WW + cxA) * CIN + ch));
        float2 vB = __ldg((const float2*)(fbt + (size_t)(cyB * WW + cxB) * CIN + ch));
        a[0] = f2tf32(vA.x * mA); a[1] = f2tf32(vB.x * mB);
        a[2] = f2tf32(vA.y * mA); a[3] = f2tf32(vB.y * mB);
    };

    uint32_t a0[4], a1[4];
    build_a(0, a0);
    build_a(1, a1);

    const float2* bp = g_bfrag + lane;

#pragma unroll 1
    for (int t = 0; t < 72; t++) {
        uint32_t an[4] = {0u, 0u, 0u, 0u};
        if (t < 70) build_a(t + 2, an);

        const float2* bt = bp + (size_t)t * 27 * 32;
#pragma unroll
        for (int g9 = 0; g9 < 3; g9++) {
            float2 bb[9];
#pragma unroll
            for (int j = 0; j < 9; j++)
                bb[j] = __ldg(bt + (g9 * 9 + j) * 32);
#pragma unroll
            for (int j = 0; j < 9; j++)
                MMA_TF32(acc[g9 * 9 + j], a0,
                         __float_as_uint(bb[j].x), __float_as_uint(bb[j].y));
        }

#pragma unroll
        for (int j = 0; j < 4; j++) { a0[j] = a1[j]; a1[j] = an[j]; }
    }

#pragma unroll
    for (int nt = 0; nt < 27; nt++) {
#pragma unroll
        for (int i = 0; i < 4; i++) {
            int p  = (i >= 2) ? pB : pA;
            int co = nt * 8 + c2 + (i & 1);
            emit_off(co, acc[nt][i], b, p, b_off);
        }
    }
}

// ---------------------------------------------------------------------------
// Kernel B: modulated deformable conv via mma.sync tf32, NHWC gathers,
// TILE_M=64, 128 thr (2 blocks/SM); warp-rotated N, 2-deep prefetch
// ---------------------------------------------------------------------------
__global__ __launch_bounds__(128)
void dcn_mma(const float* __restrict__ b_dcn,
             float* __restrict__ out)
{
    const int tid  = threadIdx.x;
    const int warp = tid >> 5, lane = tid & 31;
    const int b  = blockIdx.y;
    const int p0 = blockIdx.x * 64;
    const int rot = warp & 7;

    const int m0 = warp * 16 + (lane >> 2);
    const int pA = p0 + m0, pB = pA + 8;
    const int yA = pA / WW, xA = pA % WW;
    const int yB = pB / WW, xB = pB % WW;

    const float* dyp = g_scr;
    const float* dxp = g_scr + SCR_N;
    const float* mp  = g_scr + 2*SCR_N;
    const float* xtb = g_xt + (size_t)b * HW * CIN;

    float acc[8][4];
#pragma unroll
    for (int i = 0; i < 8; i++)
#pragma unroll
        for (int j = 0; j < 4; j++) acc[i][j] = 0.f;

    const int c = lane & 3;

    auto build_a = [&](int t, uint32_t* a) {
        int g = t / 9, k = t - g * 9;
        int kdy = (k > 5) ? 2 : ((k > 2) ? 1 : 0);
        int kdx = k - kdy * 3;
        const int sb = (b * 72 + t) * HW;
        const float* xc = xtb + g * 8 + c;

        float vA0, vA4, vB0, vB4;
        {   // row pA
            float dy = __ldg(dyp + sb + pA), dx = __ldg(dxp + sb + pA);
            float mv = __ldg(mp + sb + pA);
            float py = (float)(yA + kdy - 1) + dy;
            float px = (float)(xA + kdx - 1) + dx;
            float fy = floorf(py), fx = floorf(px);
            int y0 = (int)fy, x0 = (int)fx;
            float ly = py - fy, lx = px - fx;
            bool vy0 = ((unsigned)y0 < HH), vy1 = ((unsigned)(y0+1) < HH);
            bool vx0 = ((unsigned)x0 < WW), vx1 = ((unsigned)(x0+1) < WW);
            int y0c = min(max(y0,0),HH-1), y1c = min(max(y0+1,0),HH-1);
            int x0c = min(max(x0,0),WW-1), x1c = min(max(x0+1,0),WW-1);
            float w00 = (1.f-ly)*(1.f-lx)*mv*((vy0&&vx0)?1.f:0.f);
            float w01 = (1.f-ly)*lx      *mv*((vy0&&vx1)?1.f:0.f);
            float w10 = ly      *(1.f-lx)*mv*((vy1&&vx0)?1.f:0.f);
            float w11 = ly      *lx      *mv*((vy1&&vx1)?1.f:0.f);
            int i00 = (y0c*WW+x0c)*CIN, i01 = (y0c*WW+x1c)*CIN;
            int i10 = (y1c*WW+x0c)*CIN, i11 = (y1c*WW+x1c)*CIN;
            vA0 = w00*__ldg(xc+i00)+w01*__ldg(xc+i01)+w10*__ldg(xc+i10)+w11*__ldg(xc+i11);
            vA4 = w00*__ldg(xc+i00+4)+w01*__ldg(xc+i01+4)+w10*__ldg(xc+i10+4)+w11*__ldg(xc+i11+4);
        }
        {   // row pB
            float dy = __ldg(dyp + sb + pB), dx = __ldg(dxp + sb + pB);
            float mv = __ldg(mp + sb + pB);
            float py = (float)(yB + kdy - 1) + dy;
            float px = (float)(xB + kdx - 1) + dx;
            float fy = floorf(py), fx = floorf(px);
            int y0 = (int)fy, x0 = (int)fx;
            float ly = py - fy, lx = px - fx;
            bool vy0 = ((unsigned)y0 < HH), vy1 = ((unsigned)(y0+1) < HH);
            bool vx0 = ((unsigned)x0 < WW), vx1 = ((unsigned)(x0+1) < WW);
            int y0c = min(max(y0,0),HH-1), y1c = min(max(y0+1,0),HH-1);
            int x0c = min(max(x0,0),WW-1), x1c = min(max(x0+1,0),WW-1);
            float w00 = (1.f-ly)*(1.f-lx)*mv*((vy0&&vx0)?1.f:0.f);
            float w01 = (1.f-ly)*lx      *mv*((vy0&&vx1)?1.f:0.f);
            float w10 = ly      *(1.f-lx)*mv*((vy1&&vx0)?1.f:0.f);
            float w11 = ly      *lx      *mv*((vy1&&vx1)?1.f:0.f);
            int i00 = (y0c*WW+x0c)*CIN, i01 = (y0c*WW+x1c)*CIN;
            int i10 = (y1c*WW+x0c)*CIN, i11 = (y1c*WW+x1c)*CIN;
            vB0 = w00*__ldg(xc+i00)+w01*__ldg(xc+i01)+w10*__ldg(xc+i10)+w11*__ldg(xc+i11);
            vB4 = w00*__ldg(xc+i00+4)+w01*__ldg(xc+i01+4)+w10*__ldg(xc+i10+4)+w11*__ldg(xc+i11+4);
        }
        a[0] = f2tf32(vA0); a[1] = f2tf32(vB0);
        a[2] = f2tf32(vA4); a[3] = f2tf32(vB4);
    };

    uint32_t a0[4], a1[4];
    build_a(0, a0);
    build_a(1, a1);

    const float2* bp = g_bfrag2 + lane;

#pragma unroll 1
    for (int t = 0; t < 72; t++) {
        uint32_t an[4] = {0u, 0u, 0u, 0u};
        if (t < 70) build_a(t + 2, an);

        const float2* bt = bp + (size_t)t * 8 * 32;
#pragma unroll
        for (int i = 0; i < 8; i++) {
            int nt = (i + rot) & 7;
            float2 bb = __ldg(bt + nt * 32);
            MMA_TF32(acc[i], a0, __float_as_uint(bb.x), __float_as_uint(bb.y));
        }

#pragma unroll
        for (int j = 0; j < 4; j++) { a0[j] = a1[j]; a1[j] = an[j]; }
    }

#pragma unroll
    for (int i = 0; i < 8; i++) {
        int nt = (i + rot) & 7;
#pragma unroll
        for (int e = 0; e < 4; e++) {
            int o = nt * 8 + c * 2 + (e & 1);
            int p = (e >= 2) ? pB : pA;
            out[((size_t)b * 64 + o) * HW + p] = acc[i][e] + __ldg(b_dcn + o);
        }
    }
}

// ---------------------------------------------------------------------------
extern "C" void kernel_launch(void* const* d_in, const int* in_sizes, int n_in,
                              void* d_out, int out_size)
{
    const float* x     = (const float*)d_in[0];
    const float* feat  = (const float*)d_in[1];
    const float* w_off = (const float*)d_in[2];
    const float* b_off = (const float*)d_in[3];
    const float* w_dcn = (const float*)d_in[4];
    const float* b_dcn = (const float*)d_in[5];
    float* out = (float*)d_out;

    pack_w_kernel<<<(NBT + 255) / 256, 256>>>(w_off);
    pack_wd_kernel<<<(NBT2 + 255) / 256, 256>>>(w_dcn);

    dim3 gT(HW / 32, CIN / 32, BATCH * 2);  // 800 x 2 x 8 (x + feat)
    transpose2_kernel<<<gT, 256>>>(x, feat);

    dim3 gA(HW / 64, BATCH);            // 400 x 4
    offset_conv_mma<<<gA, 128>>>(b_off);

    dim3 gB(HW / 64, BATCH);            // 400 x 4
    dcn_mma<<<gB, 128>>>(b_dcn, out);
}